// round 2
// baseline (speedup 1.0000x reference)
#include <cuda_runtime.h>

#define VOCAB 8000
#define C 256
#define P 8
#define BB 16
#define LL 2048
#define T 64                 // positions per block tile
#define ROWS (T + 2*P)       // 80 staged embedding rows
#define THREADS 256
#define SMEM_BYTES ((ROWS*C + T*16 + T) * 4)   // 86272 bytes

__global__ void gnn_zero_out(float* out) {
    out[blockIdx.x * blockDim.x + threadIdx.x] = 0.0f;
}

__global__ __launch_bounds__(THREADS, 2)
void gnn_kernel(const int* __restrict__ ids,
                const float* __restrict__ emb,
                const float* __restrict__ ew,
                const float* __restrict__ nw,
                float* __restrict__ out)
{
    extern __shared__ float smem[];
    float* rows_s = smem;                 // [ROWS][C]
    float* W_s    = smem + ROWS * C;      // [T][16]
    float* NN_s   = W_s + T * 16;         // [T]

    const int b  = blockIdx.y;
    const int l0 = blockIdx.x * T;
    const int* idrow = ids + b * LL;
    const int tid = threadIdx.x;

    // ---- Phase 1a: stage T+16 embedding rows into SMEM (float4, coalesced) ----
    for (int e = tid; e < ROWS * (C / 4); e += THREADS) {
        int i  = e / (C / 4);
        int c4 = e % (C / 4);
        int p  = l0 - P + i;
        int nx = (p >= 0 && p < LL) ? idrow[p] : 0;   // row 0 of emb is all-zero
        float4 v = reinterpret_cast<const float4*>(emb + (size_t)nx * C)[c4];
        reinterpret_cast<float4*>(rows_s + i * C)[c4] = v;
    }

    // ---- Phase 1b: gather edge weights (random DRAM gather) + node weights ----
    for (int e = tid; e < T * 16; e += THREADS) {
        int t = e >> 4, j = e & 15;
        int l = l0 + t;
        int off = (j < P) ? (j - P) : (j - P + 1);    // {-8..-1, 1..8}
        int p = l + off;
        int nx = (p >= 0 && p < LL) ? idrow[p] : 0;
        int id = idrow[l];
        // when nx==0 the product is 0 (emb row 0 == 0), so the gathered weight
        // value is irrelevant; index id*VOCAB+nx is always in-bounds.
        W_s[e] = ew[(size_t)id * VOCAB + nx];
    }
    for (int t = tid; t < T; t += THREADS) {
        NN_s[t] = nw[idrow[l0 + t]];
    }
    __syncthreads();

    // ---- Phase 2: 4 position-subgroups x 64 channel-threads (4 ch each) ----
    const int g  = tid >> 6;        // subgroup 0..3 -> positions g, g+4, ...
    const int ct = tid & 63;        // channel thread
    const int c  = ct * 4;

    float acc0 = 0.f, acc1 = 0.f, acc2 = 0.f, acc3 = 0.f;

    for (int t = g; t < T; t += 4) {
        float w[16];
        #pragma unroll
        for (int j = 0; j < 16; j++) w[j] = W_s[t * 16 + j];   // broadcast LDS
        float nn = NN_s[t];

        float m0 = -3.402823466e38f, m1 = -3.402823466e38f;
        float m2 = -3.402823466e38f, m3 = -3.402823466e38f;

        #pragma unroll
        for (int j = 0; j < 16; j++) {
            int i = t + j + (j >= P ? 1 : 0);   // smem row = t + off + P
            float4 v = reinterpret_cast<const float4*>(rows_s + i * C + c)[0];
            m0 = fmaxf(m0, v.x * w[j]);
            m1 = fmaxf(m1, v.y * w[j]);
            m2 = fmaxf(m2, v.z * w[j]);
            m3 = fmaxf(m3, v.w * w[j]);
        }

        float4 rn = reinterpret_cast<const float4*>(rows_s + (t + P) * C + c)[0];
        float one_nn = 1.0f - nn;
        acc0 += one_nn * m0 + nn * rn.x;
        acc1 += one_nn * m1 + nn * rn.y;
        acc2 += one_nn * m2 + nn * rn.z;
        acc3 += one_nn * m3 + nn * rn.w;
    }

    atomicAdd(&out[b * C + c + 0], acc0);
    atomicAdd(&out[b * C + c + 1], acc1);
    atomicAdd(&out[b * C + c + 2], acc2);
    atomicAdd(&out[b * C + c + 3], acc3);
}

extern "C" void kernel_launch(void* const* d_in, const int* in_sizes, int n_in,
                              void* d_out, int out_size) {
    const int*   ids = (const int*)  d_in[0];
    const float* emb = (const float*)d_in[1];
    const float* ew  = (const float*)d_in[2];
    const float* nw  = (const float*)d_in[3];
    float* out = (float*)d_out;

    gnn_zero_out<<<BB, C>>>(out);   // out poisoned to 0xAA -> zero first

    cudaFuncSetAttribute(gnn_kernel,
                         cudaFuncAttributeMaxDynamicSharedMemorySize, SMEM_BYTES);
    dim3 grid(LL / T, BB);
    gnn_kernel<<<grid, THREADS, SMEM_BYTES>>>(ids, emb, ew, nw, out);
}

// round 3
// speedup vs baseline: 1.8915x; 1.8915x over previous
#include <cuda_runtime.h>
#include <float.h>

#define VOCAB 8000
#define C 256
#define P 8
#define BB 16
#define LL 2048
#define T 64                  // positions per block tile
#define ROWS (T + 2*P)        // 80 neighbor ids staged
#define THREADS 256
#define POS_PER 32            // positions per subgroup (T / 2 subgroups)

__global__ void gnn_zero_out(float* out) {
    out[blockIdx.x * blockDim.x + threadIdx.x] = 0.0f;
}

__global__ __launch_bounds__(THREADS, 3)
void gnn_kernel(const int* __restrict__ ids,
                const float* __restrict__ emb,
                const float* __restrict__ ew,
                const float* __restrict__ nw,
                float* __restrict__ out)
{
    __shared__ float W_s[T * 16];   // edge weights, [pos][j]
    __shared__ float NN_s[T];       // node weights
    __shared__ int   NX_s[ROWS];    // neighbor token ids for window rows

    const int b  = blockIdx.y;
    const int l0 = blockIdx.x * T;
    const int* idrow = ids + b * LL;
    const int tid = threadIdx.x;

    // ---- stage neighbor ids ----
    for (int i = tid; i < ROWS; i += THREADS) {
        int p = l0 - P + i;
        NX_s[i] = (p >= 0 && p < LL) ? idrow[p] : 0;
    }
    __syncthreads();

    // ---- gather edge weights (random DRAM gather, done once, MLP=4) ----
    for (int e = tid; e < T * 16; e += THREADS) {
        int t = e >> 4, j = e & 15;
        int k = j + (j >= P);             // window slot 0..16, skipping center 8
        int nx = NX_s[t + k];
        int id = NX_s[t + P];             // center token = idrow[l0+t]
        // nx==0 -> emb row 0 is all-zero -> product 0 regardless of weight value
        W_s[e] = ew[(size_t)id * VOCAB + nx];
    }
    for (int t = tid; t < T; t += THREADS)
        NN_s[t] = nw[NX_s[t + P]];
    __syncthreads();

    // ---- phase 2: register sliding window over positions ----
    const int g    = tid >> 7;            // subgroup 0/1 -> contiguous 32 positions
    const int ct   = tid & 127;           // channel thread: channels 2ct, 2ct+1
    const int base = g * POS_PER;
    const float2* __restrict__ e2 = (const float2*)emb;

    // window: win[(r) % 17] holds emb[NX_s[base + r]] channels {2ct, 2ct+1}
    float2 win[17];
    #pragma unroll
    for (int k = 0; k < 17; k++)
        win[k] = e2[(size_t)NX_s[base + k] * (C / 2) + ct];
    float2 nxt = e2[(size_t)NX_s[base + 17] * (C / 2) + ct];

    float acc0 = 0.f, acc1 = 0.f;

    #pragma unroll
    for (int tt = 0; tt < POS_PER; tt++) {
        // broadcast weight loads (4x LDS.128)
        const float4* wv = (const float4*)(W_s + (base + tt) * 16);
        float4 wa = wv[0], wb = wv[1], wc = wv[2], wd = wv[3];
        float nn = NN_s[base + tt];

        float m0 = -FLT_MAX, m1 = -FLT_MAX;
        #define STEP(j, wreg) { \
            float2 v = win[(tt + (j) + ((j) >= 8 ? 1 : 0)) % 17]; \
            m0 = fmaxf(m0, v.x * (wreg)); \
            m1 = fmaxf(m1, v.y * (wreg)); }
        STEP(0,  wa.x) STEP(1,  wa.y) STEP(2,  wa.z) STEP(3,  wa.w)
        STEP(4,  wb.x) STEP(5,  wb.y) STEP(6,  wb.z) STEP(7,  wb.w)
        STEP(8,  wc.x) STEP(9,  wc.y) STEP(10, wc.z) STEP(11, wc.w)
        STEP(12, wd.x) STEP(13, wd.y) STEP(14, wd.z) STEP(15, wd.w)
        #undef STEP

        float2 rn = win[(tt + 8) % 17];
        float on = 1.0f - nn;
        acc0 += on * m0 + nn * rn.x;
        acc1 += on * m1 + nn * rn.y;

        // slide: slot tt%17 (held row base+tt, now dead) <- prefetched row base+tt+17
        if (tt < POS_PER - 1) {
            win[tt % 17] = nxt;
            if (tt < POS_PER - 2)
                nxt = e2[(size_t)NX_s[base + tt + 18] * (C / 2) + ct];
        }
    }

    atomicAdd(&out[b * C + 2 * ct + 0], acc0);
    atomicAdd(&out[b * C + 2 * ct + 1], acc1);
}

extern "C" void kernel_launch(void* const* d_in, const int* in_sizes, int n_in,
                              void* d_out, int out_size) {
    const int*   ids = (const int*)  d_in[0];
    const float* emb = (const float*)d_in[1];
    const float* ew  = (const float*)d_in[2];
    const float* nw  = (const float*)d_in[3];
    float* out = (float*)d_out;

    gnn_zero_out<<<BB, C>>>(out);   // d_out poisoned to 0xAA -> zero first

    dim3 grid(LL / T, BB);
    gnn_kernel<<<grid, THREADS>>>(ids, emb, ew, nw, out);
}